// round 17
// baseline (speedup 1.0000x reference)
#include <cuda_runtime.h>

#define BB    512
#define SEQL  96
#define PREDL 48
#define TOTL  144
#define CIN   7
#define DM    128
#define G3    384
#define KSZ   5
#define PADL  2
#define NWIN  48
#define WCONV (KSZ*DM*DM)   // 81920
#define MAINBK 768          // 512*96 main rows / 64 per block

// ---------------- device scratch ----------------
__device__ float g_temb[BB * TOTL * DM];
__device__ float g_xcat[BB * TOTL * CIN];
__device__ float g_emb [BB * TOTL * DM];
__device__ float g_c1  [BB * TOTL * DM];
__device__ float g_c2  [BB * TOTL * DM];
__device__ float g_c3  [BB * TOTL * DM];
__device__ float g_gx  [BB * TOTL * G3];
__device__ float g_lbgx[(size_t)PREDL * BB * 6 * G3];
__device__ float g_lb1 [BB * NWIN * 2 * DM];
__device__ float g_lb2 [BB * NWIN * 4 * DM];
__device__ float g_lb3 [BB * NWIN * 6 * DM];
__device__ float g_wc  [3 * WCONV];          // [sel][tap*128+ic][o]
__device__ float g_wvt [CIN * DM];
__device__ float g_wit [DM * G3];            // Wi^T [d][g]

__device__ __forceinline__ void ffma2(unsigned long long& acc,
                                      unsigned long long a, unsigned long long w) {
    asm("fma.rn.f32x2 %0, %1, %2, %0;" : "+l"(acc) : "l"(a), "l"(w));
}
__device__ __forceinline__ float sum2(unsigned long long v) {
    float2 f = *reinterpret_cast<float2*>(&v);
    return f.x + f.y;
}

// ---------------- prep (merged; R16-verbatim) ----------------
__global__ void prep1_kernel(const float* __restrict__ w1, const float* __restrict__ w2,
                             const float* __restrict__ w3, const float* __restrict__ wval,
                             const float* __restrict__ wi, const float* __restrict__ xenc) {
    int idx = blockIdx.x * 256 + threadIdx.x;
    if (idx < WCONV) {
        int r = idx / DM, o = idx - r * DM;
        int k = r / DM,  i = r - k * DM;
        int s = (o * DM + i) * KSZ + k;
        g_wc[idx]             = w1[s];
        g_wc[WCONV + idx]     = w2[s];
        g_wc[2 * WCONV + idx] = w3[s];
    }
    if (idx < DM * G3) {
        int d = idx / G3, g = idx - d * G3;
        g_wit[idx] = wi[g * DM + d];
    }
    if (idx < CIN * DM) {
        int c = idx / DM, d = idx - c * DM;
        g_wvt[idx] = wval[d * CIN + c];
    }
    if (idx < BB * TOTL * CIN) {
        int c = idx % CIN;
        int t = (idx / CIN) % TOTL;
        int b = idx / (CIN * TOTL);
        g_xcat[idx] = (t < SEQL) ? xenc[(b * SEQL + t) * CIN + c] : 0.f;
    }
}

__global__ void prep2_kernel(const int* __restrict__ ymark,
                             const float* __restrict__ hour, const float* __restrict__ wk,
                             const float* __restrict__ day,  const float* __restrict__ mon,
                             const float* __restrict__ bval) {
    int bl = blockIdx.x;                  // b*TOTL + l
    int b = bl / TOTL, l = bl - b * TOTL;
    int d = threadIdx.x;
    __shared__ float xs[CIN];
    if (d < CIN && l < SEQL) xs[d] = g_xcat[bl * CIN + d];
    const int* y = ymark + bl * 4;
    float te = hour[y[0] * DM + d] + wk[y[1] * DM + d]
             + day [y[2] * DM + d] + mon[y[3] * DM + d];
    g_temb[bl * DM + d] = te;
    __syncthreads();
    if (l < SEQL) {
        float acc = bval[d] + te;
#pragma unroll
        for (int c = 0; c < CIN; c++) acc = fmaf(xs[c], g_wvt[c * DM + d], acc);
        g_emb[bl * DM + d] = acc;
    }
}

// ---------------- fused stage GEMMs, 4x8 register tile, vectorized smem ----------------
template<int ST>
__device__ __forceinline__ float lb_fetch(int b, int win, int a, int ic) {
    if (ST == 0) return (a >= 0) ? g_emb[((size_t)b * TOTL + win + a) * DM + ic] : 0.f;
    if (ST == 1) {
        if (a < 0) return 0.f;
        return (a < 2) ? g_lb1[(((size_t)b * NWIN + win) * 2 + a) * DM + ic]
                       : g_c1[((size_t)b * TOTL + win + a) * DM + ic];
    }
    if (a < 0) return 0.f;
    return (a < 4) ? g_lb2[(((size_t)b * NWIN + win) * 4 + a) * DM + ic]
                   : g_c2[((size_t)b * TOTL + win + a) * DM + ic];
}

// 64 rows/block; blocks [0, MAINBK) are main rows (b*96+p), the rest lb rows.
// ST 0/1/2: conv (N=128, KC=40, relu). ST 3: gx (N=384 via blockIdx.y, KC=8).
template<int ST>
__global__ __launch_bounds__(256) void stage_kernel(const float* __restrict__ bias) {
    constexpr bool GX  = (ST == 3);
    constexpr int KC   = GX ? 8 : 40;
    constexpr int NW   = GX ? G3 : DM;
    constexpr int NPOS = (ST == 0) ? 2 : (ST == 1) ? 4 : 6;

    __shared__ __align__(16) float As[16][68];   // [kk][row], 68 keeps 16B-aligned rows
    __shared__ __align__(16) float Bs[16][DM];   // [kk][o]

    int tid  = threadIdx.x;
    int gk   = tid & 15;          // fill: kk
    int gr4  = (tid >> 4) * 4;    // fill/compute: first of this thread's 4 rows
    int txc8 = (tid & 15) * 8;    // compute: first of this thread's 8 cols
    int ncol0 = blockIdx.y * DM;
    const float* __restrict__ w = GX ? g_wit : (g_wc + ST * WCONV);
    const float* __restrict__ src =
        (ST == 0) ? g_emb : (ST == 1) ? g_c1 : g_c2;

    const bool isMain = blockIdx.x < MAINBK;
    int bx = isMain ? blockIdx.x : blockIdx.x - MAINBK;

    // decode this thread's 4 rows (same rows for fill and compute: tid>>4)
    int rb[4], rp[4], rw[4];
#pragma unroll
    for (int m = 0; m < 4; m++) {
        int R = bx * 64 + gr4 + m;
        if (isMain) { rb[m] = R / SEQL; rp[m] = R - rb[m] * SEQL; rw[m] = 0; }
        else {
            rp[m] = R % NPOS;
            int wb = R / NPOS;
            rw[m] = wb % NWIN;
            rb[m] = wb / NWIN;
        }
    }

    float acc[4][8];
#pragma unroll
    for (int m = 0; m < 4; m++)
#pragma unroll
        for (int n = 0; n < 8; n++) acc[m][n] = 0.f;

    for (int kc = 0; kc < KC; kc++) {
        int tap = kc >> 3;
        int icb = ((kc & 7) << 4);
        int ic  = icb + gk;
        // ---- As fill: 4 gathers (coalesced 64B per row across gk lanes) ----
#pragma unroll
        for (int m = 0; m < 4; m++) {
            float v;
            if (GX) {
                v = isMain
                    ? g_c3[((size_t)rb[m] * TOTL + rp[m]) * DM + ic]
                    : g_lb3[(((size_t)rb[m] * NWIN + rw[m]) * 6 + rp[m]) * DM + ic];
            } else if (isMain) {
                int q = rp[m] - PADL + tap;
                v = (q >= 0 && q < SEQL)
                    ? src[((size_t)rb[m] * TOTL + q) * DM + ic] : 0.f;
            } else {
                v = lb_fetch<GX ? 2 : ST>(rb[m], rw[m], rp[m] + tap - PADL, ic);
            }
            As[gk][gr4 + m] = v;
        }
        // ---- Bs fill: 2x LDG.128 + STS.128 per thread ----
#pragma unroll
        for (int j = 0; j < 2; j++) {
            int e  = tid * 2 + j;          // 512 float4 chunks
            int kk = e >> 5, o4 = (e & 31) << 2;
            float4 wv = *reinterpret_cast<const float4*>(
                            w + (size_t)(kc * 16 + kk) * NW + ncol0 + o4);
            *reinterpret_cast<float4*>(&Bs[kk][o4]) = wv;
        }
        __syncthreads();
#pragma unroll
        for (int rr = 0; rr < 16; rr++) {
            float4 a  = *reinterpret_cast<const float4*>(&As[rr][gr4]);
            float4 b0 = *reinterpret_cast<const float4*>(&Bs[rr][txc8]);
            float4 b1 = *reinterpret_cast<const float4*>(&Bs[rr][txc8 + 4]);
            float av[4] = {a.x, a.y, a.z, a.w};
            float bv[8] = {b0.x, b0.y, b0.z, b0.w, b1.x, b1.y, b1.z, b1.w};
#pragma unroll
            for (int m = 0; m < 4; m++)
#pragma unroll
                for (int n = 0; n < 8; n++)
                    acc[m][n] = fmaf(av[m], bv[n], acc[m][n]);
        }
        __syncthreads();
    }

    // ---- writeback: per row, 2x STG.128 ----
    float4 bia0 = *reinterpret_cast<const float4*>(bias + ncol0 + txc8);
    float4 bia1 = *reinterpret_cast<const float4*>(bias + ncol0 + txc8 + 4);
#pragma unroll
    for (int m = 0; m < 4; m++) {
        float4 v0, v1;
        v0.x = acc[m][0] + bia0.x; v0.y = acc[m][1] + bia0.y;
        v0.z = acc[m][2] + bia0.z; v0.w = acc[m][3] + bia0.w;
        v1.x = acc[m][4] + bia1.x; v1.y = acc[m][5] + bia1.y;
        v1.z = acc[m][6] + bia1.z; v1.w = acc[m][7] + bia1.w;
        if (!GX) {
            v0.x = fmaxf(v0.x, 0.f); v0.y = fmaxf(v0.y, 0.f);
            v0.z = fmaxf(v0.z, 0.f); v0.w = fmaxf(v0.w, 0.f);
            v1.x = fmaxf(v1.x, 0.f); v1.y = fmaxf(v1.y, 0.f);
            v1.z = fmaxf(v1.z, 0.f); v1.w = fmaxf(v1.w, 0.f);
        }
        float* dp;
        if (GX) {
            dp = isMain
                ? g_gx + ((size_t)rb[m] * TOTL + rp[m]) * G3 + ncol0 + txc8
                : g_lbgx + (((size_t)rw[m] * BB + rb[m]) * 6 + rp[m]) * G3 + ncol0 + txc8;
        } else if (isMain) {
            float* dst = (ST == 0) ? g_c1 : (ST == 1) ? g_c2 : g_c3;
            dp = dst + ((size_t)rb[m] * TOTL + rp[m]) * DM + txc8;
        } else {
            float* dst = (ST == 0) ? g_lb1 : (ST == 1) ? g_lb2 : g_lb3;
            dp = dst + (((size_t)rb[m] * NWIN + rw[m]) * NPOS + rp[m]) * DM + txc8;
        }
        *reinterpret_cast<float4*>(dp)     = v0;
        *reinterpret_cast<float4*>(dp + 4) = v1;
    }
}

// ---------------- prologue conv stage (R10/R16-verbatim) ----------------
template<int NPOS>
__device__ __forceinline__ void prolog_stage(int b0, int F,
        const float* __restrict__ src, const float* __restrict__ wp,
        const float* __restrict__ bias, float* __restrict__ dst,
        float* sA4, float* sRedA, float* sRedB,
        int tid, int o, int g, int ic0, int ic1) {
    constexpr int NR = NPOS + 2;
    for (int e = tid; e < 4 * NR * DM; e += 384) {
        int ic = e & 127, ra = e >> 7;
        int r = ra / NR, a = ra - r * NR;
        sA4[e] = src[((size_t)(b0 + r) * TOTL + F - (NR - 1) + a) * DM + ic];
    }
    __syncthreads();
    float acc[NPOS][4];
#pragma unroll
    for (int p = 0; p < NPOS; p++)
#pragma unroll
        for (int r = 0; r < 4; r++) acc[p][r] = 0.f;
    for (int ic = ic0; ic < ic1; ic++) {
        float xv[4][NR];
#pragma unroll
        for (int r = 0; r < 4; r++)
#pragma unroll
            for (int a = 0; a < NR; a++) xv[r][a] = sA4[(r * NR + a) * DM + ic];
#pragma unroll
        for (int tap = 0; tap < 5; tap++) {
            float w = wp[(size_t)(tap * DM + ic) * DM + o];
#pragma unroll
            for (int p = 0; p < NPOS; p++) {
                const int a = p + tap;
                if (a <= NPOS + 1) {
#pragma unroll
                    for (int r = 0; r < 4; r++)
                        acc[p][r] = fmaf(w, xv[r][a], acc[p][r]);
                }
            }
        }
    }
    for (int r = 0; r < 4; r++) {
        if (g == 1) {
#pragma unroll
            for (int p = 0; p < NPOS; p++) sRedA[p * DM + o] = acc[p][r];
        } else if (g == 2) {
#pragma unroll
            for (int p = 0; p < NPOS; p++) sRedB[p * DM + o] = acc[p][r];
        }
        __syncthreads();
        if (g == 0) {
#pragma unroll
            for (int p = 0; p < NPOS; p++) {
                float v = acc[p][r] + sRedA[p * DM + o] + sRedB[p * DM + o] + bias[o];
                dst[((size_t)(b0 + r) * TOTL + F - (NPOS - 1) + p) * DM + o] = fmaxf(v, 0.f);
            }
        }
        __syncthreads();
    }
}

// ---------------- persistent loop: 48 steps (R16-verbatim) ----------------
__global__ __launch_bounds__(384, 1) void loop_kernel(
        const float* __restrict__ Wh,  const float* __restrict__ bh,
        const float* __restrict__ fcw, const float* __restrict__ fcb,
        const float* __restrict__ bval,
        const float* __restrict__ c1b, const float* __restrict__ c2b,
        const float* __restrict__ c3b, const float* __restrict__ gbi,
        float* __restrict__ dout) {
    int tid = threadIdx.x;
    int b0  = blockIdx.x * 4;

    __shared__ __align__(16) float h_s[4][DM];
    __shared__ float S1[4][G3];
    __shared__ float S2[4][DM];
    __shared__ float sPred[4][CIN];
    __shared__ __align__(16) float sA4[4 * 9 * DM];
    __shared__ float sRedA[7 * DM];
    __shared__ float sRedB[7 * DM];

    for (int i = 0; i < PREDL; i++) {
        if (i > 0) {
            __syncthreads();
            const int F  = SEQL - 1 + i;
            const int o  = tid & 127;
            const int g  = tid >> 7;
            const int ic0 = (g == 0) ? 0 : (g == 1) ? 43 : 86;
            const int ic1 = (g == 0) ? 43 : (g == 1) ? 86 : 128;

            for (int e = tid; e < 4 * DM; e += 384) {
                int r = e >> 7, d = e & 127;
                int b = b0 + r;
                float a = bval[d] + g_temb[((size_t)b * TOTL + F) * DM + d];
#pragma unroll
                for (int c = 0; c < CIN; c++) a = fmaf(sPred[r][c], g_wvt[c * DM + d], a);
                g_emb[((size_t)b * TOTL + F) * DM + d] = a;
            }
            __syncthreads();

            prolog_stage<3>(b0, F, g_emb, g_wc,             c1b, g_c1, sA4, sRedA, sRedB, tid, o, g, ic0, ic1);
            prolog_stage<5>(b0, F, g_c1,  g_wc + WCONV,     c2b, g_c2, sA4, sRedA, sRedB, tid, o, g, ic0, ic1);
            prolog_stage<7>(b0, F, g_c2,  g_wc + 2 * WCONV, c3b, g_c3, sA4, sRedA, sRedB, tid, o, g, ic0, ic1);

            for (int e = tid; e < 4 * 7 * DM; e += 384) {
                int ic = e & 127, rp = e >> 7;
                int r = rp / 7, p = rp - r * 7;
                sA4[e] = g_c3[((size_t)(b0 + r) * TOTL + F - 6 + p) * DM + ic];
            }
            __syncthreads();
            {
                int rq = tid / 96, cq = tid - rq * 96;
                float acc[7][4];
#pragma unroll
                for (int p = 0; p < 7; p++)
#pragma unroll
                    for (int c = 0; c < 4; c++) acc[p][c] = 0.f;
                const float4* wv = reinterpret_cast<const float4*>(g_wit) + cq;
                const float* xb = sA4 + rq * 7 * DM;
                for (int k = 0; k < DM; k++) {
                    float4 w = wv[(size_t)k * 96];
                    float x[7];
#pragma unroll
                    for (int p = 0; p < 7; p++) x[p] = xb[p * DM + k];
#pragma unroll
                    for (int p = 0; p < 7; p++) {
                        acc[p][0] = fmaf(w.x, x[p], acc[p][0]);
                        acc[p][1] = fmaf(w.y, x[p], acc[p][1]);
                        acc[p][2] = fmaf(w.z, x[p], acc[p][2]);
                        acc[p][3] = fmaf(w.w, x[p], acc[p][3]);
                    }
                }
                float4 bo = reinterpret_cast<const float4*>(gbi)[cq];
#pragma unroll
                for (int p = 0; p < 7; p++) {
                    float4 v;
                    v.x = acc[p][0] + bo.x; v.y = acc[p][1] + bo.y;
                    v.z = acc[p][2] + bo.z; v.w = acc[p][3] + bo.w;
                    *reinterpret_cast<float4*>(
                        g_gx + ((size_t)(b0 + rq) * TOTL + F - 6 + p) * G3 + cq * 4) = v;
                }
            }
            __syncthreads();
        }

        // ---- GRU t-loop ----
        int j = tid;
        ulonglong2 wr[32];
        {
            const ulonglong2* p = reinterpret_cast<const ulonglong2*>(Wh + (size_t)j * DM);
#pragma unroll
            for (int q = 0; q < 32; q++) wr[q] = p[q];
        }
        float bhj = bh[j];

        for (int e = j; e < 4 * DM; e += 384) (&h_s[0][0])[e] = 0.f;
        __syncthreads();

        for (int t = 0; t < SEQL; t++) {
            float gxv[4];
#pragma unroll
            for (int r = 0; r < 4; r++) {
                int b = b0 + r;
                gxv[r] = (t < 6)
                    ? g_lbgx[(((size_t)i * BB + b) * 6 + t) * G3 + j]
                    : g_gx[((size_t)b * TOTL + i + t) * G3 + j];
            }
            unsigned long long c0 = 0, c1 = 0, c2 = 0, c3 = 0;
            const ulonglong2* h0 = reinterpret_cast<const ulonglong2*>(h_s[0]);
            const ulonglong2* h1 = reinterpret_cast<const ulonglong2*>(h_s[1]);
            const ulonglong2* h2 = reinterpret_cast<const ulonglong2*>(h_s[2]);
            const ulonglong2* h3 = reinterpret_cast<const ulonglong2*>(h_s[3]);
#pragma unroll
            for (int q = 0; q < 32; q++) {
                ulonglong2 w  = wr[q];
                ulonglong2 x0 = h0[q], x1 = h1[q], x2 = h2[q], x3 = h3[q];
                ffma2(c0, x0.x, w.x); ffma2(c0, x0.y, w.y);
                ffma2(c1, x1.x, w.x); ffma2(c1, x1.y, w.y);
                ffma2(c2, x2.x, w.x); ffma2(c2, x2.y, w.y);
                ffma2(c3, x3.x, w.x); ffma2(c3, x3.y, w.y);
            }
            float accs[4] = {sum2(c0), sum2(c1), sum2(c2), sum2(c3)};
#pragma unroll
            for (int r = 0; r < 4; r++) {
                float gh = accs[r] + bhj;
                if (j < 2 * DM) S1[r][j] = gxv[r] + gh;
                else            { S1[r][j] = gh; S2[r][j - 2 * DM] = gxv[r]; }
            }
            __syncthreads();
            for (int e = j; e < 4 * DM; e += 384) {
                int r = e >> 7, d = e & 127;
                float rg = __fdividef(1.f, 1.f + __expf(-S1[r][d]));
                float zg = __fdividef(1.f, 1.f + __expf(-S1[r][DM + d]));
                float na = S2[r][d] + rg * S1[r][2 * DM + d];
                float ng = 1.f - __fdividef(2.f, __expf(2.f * na) + 1.f);
                h_s[r][d] = (1.f - zg) * ng + zg * h_s[r][d];
            }
            __syncthreads();
        }

        if (j < 4 * CIN) {
            int r = j / CIN, c = j - r * CIN;
            float acc = fcb[c];
            for (int d = 0; d < DM; d++) acc = fmaf(h_s[r][d], fcw[c * DM + d], acc);
            sPred[r][c] = acc;
            dout[((size_t)(b0 + r) * PREDL + i) * CIN + c] = acc;
        }
    }
}

// ---------------- launcher ----------------
extern "C" void kernel_launch(void* const* d_in, const int* in_sizes, int n_in,
                              void* d_out, int out_size) {
    (void)in_sizes; (void)n_in; (void)out_size;
    const float* x_enc  = (const float*)d_in[0];
    const int*   y_mark = (const int*)  d_in[2];
    const float* hour_e = (const float*)d_in[3];
    const float* wk_e   = (const float*)d_in[4];
    const float* day_e  = (const float*)d_in[5];
    const float* mon_e  = (const float*)d_in[6];
    const float* W_val  = (const float*)d_in[7];
    const float* b_val  = (const float*)d_in[8];
    const float* c1w    = (const float*)d_in[9];
    const float* c1b    = (const float*)d_in[10];
    const float* c2w    = (const float*)d_in[11];
    const float* c2b    = (const float*)d_in[12];
    const float* c3w    = (const float*)d_in[13];
    const float* c3b    = (const float*)d_in[14];
    const float* gWi    = (const float*)d_in[15];
    const float* gWh    = (const float*)d_in[16];
    const float* gbi    = (const float*)d_in[17];
    const float* gbh    = (const float*)d_in[18];
    const float* fcw    = (const float*)d_in[19];
    const float* fcb    = (const float*)d_in[20];
    float* out = (float*)d_out;

    prep1_kernel<<<(BB * TOTL * CIN + 255) / 256, 256>>>(c1w, c2w, c3w, W_val, gWi, x_enc);
    prep2_kernel<<<BB * TOTL, DM>>>(y_mark, hour_e, wk_e, day_e, mon_e, b_val);

    // fused upfront: conv stage + paired lb cascade, 64-row blocks
    stage_kernel<0><<<MAINBK + 768,  256>>>(c1b);           // conv1 + lb0
    stage_kernel<1><<<MAINBK + 1536, 256>>>(c2b);           // conv2 + lb1
    stage_kernel<2><<<MAINBK + 2304, 256>>>(c3b);           // conv3 + lb2
    stage_kernel<3><<<dim3(MAINBK + 2304, 3), 256>>>(gbi);  // gx + lbgx

    // all 48 autoregressive steps in one persistent kernel
    loop_kernel<<<BB / 4, 384>>>(gWh, gbh, fcw, fcb, b_val, c1b, c2b, c3b, gbi, out);
}